// round 1
// baseline (speedup 1.0000x reference)
#include <cuda_runtime.h>
#include <math.h>

// Problem constants
#define BN   32
#define CC   3072
#define KK   11
#define HW   784
#define NCLS 200
#define NCH  8            // c-chunks for k_ab
#define CCH  (CC / NCH)   // 384 channels per chunk

// Scratch (device globals; no allocation allowed)
__device__ float g_ab_part[NCH * BN * KK * HW];   // 8.8 MB partial ab
__device__ float g_asq[KK];
__device__ float g_g[BN * CC];                    // sum_k feat_mod

// ---------------------------------------------------------------------------
// Kernel 0: a_sq[k] = sum_c w_land[k,c]^2
// ---------------------------------------------------------------------------
__global__ void k_asq(const float* __restrict__ wl) {
    int k = blockIdx.x;
    int tid = threadIdx.x;
    float s = 0.f;
    for (int c = tid; c < CC; c += 128) {
        float w = wl[k * CC + c];
        s += w * w;
    }
    __shared__ float red[128];
    red[tid] = s;
    __syncthreads();
    for (int o = 64; o; o >>= 1) {
        if (tid < o) red[tid] += red[tid + o];
        __syncthreads();
    }
    if (tid == 0) g_asq[k] = red[0];
}

// ---------------------------------------------------------------------------
// Kernel 1: partial ab over a 384-channel chunk.
// grid (NCH, BN), block 196 threads, each thread 4 consecutive pixels (float4)
// ---------------------------------------------------------------------------
__global__ void k_ab(const float* __restrict__ x, const float* __restrict__ wl) {
    __shared__ float ws[KK * CCH];
    const int ch = blockIdx.x;
    const int b  = blockIdx.y;
    const int c0 = ch * CCH;
    const int tid = threadIdx.x;

    for (int i = tid; i < KK * CCH; i += 196) {
        int k  = i / CCH;
        int cc = i - k * CCH;
        ws[i] = wl[k * CC + c0 + cc];
    }
    __syncthreads();

    float acc[KK][4];
#pragma unroll
    for (int k = 0; k < KK; ++k) {
        acc[k][0] = 0.f; acc[k][1] = 0.f; acc[k][2] = 0.f; acc[k][3] = 0.f;
    }

    // x[b, c0+c, 4*tid .. 4*tid+3]; row stride = 784 floats = 196 float4
    const float4* xp =
        reinterpret_cast<const float4*>(x + ((size_t)b * CC + c0) * HW) + tid;

#pragma unroll 4
    for (int c = 0; c < CCH; ++c) {
        float4 xv = xp[(size_t)c * (HW / 4)];
#pragma unroll
        for (int k = 0; k < KK; ++k) {
            float w = ws[k * CCH + c];
            acc[k][0] = fmaf(w, xv.x, acc[k][0]);
            acc[k][1] = fmaf(w, xv.y, acc[k][1]);
            acc[k][2] = fmaf(w, xv.z, acc[k][2]);
            acc[k][3] = fmaf(w, xv.w, acc[k][3]);
        }
    }

    size_t base = ((size_t)(ch * BN + b) * KK) * HW;
#pragma unroll
    for (int k = 0; k < KK; ++k) {
        float4 v = make_float4(acc[k][0], acc[k][1], acc[k][2], acc[k][3]);
        reinterpret_cast<float4*>(g_ab_part + base + (size_t)k * HW)[tid] = v;
    }
}

// ---------------------------------------------------------------------------
// Kernel 2: combine chunks, softmax over K, write maps + attn_cls.
// b_sq cancels in the softmax: maps = softmax_k(2*ab[k] - a_sq[k])
// grid 32 (per batch), block 256
// ---------------------------------------------------------------------------
__global__ void k_softmax(float* __restrict__ maps, float* __restrict__ attn) {
    const int b = blockIdx.x;
    const int tid = threadIdx.x;

    __shared__ float asq[KK];
    if (tid < KK) asq[tid] = g_asq[tid];
    __syncthreads();

    float att[KK];
#pragma unroll
    for (int k = 0; k < KK; ++k) att[k] = 0.f;

    for (int p = tid; p < HW; p += 256) {
        float s[KK];
#pragma unroll
        for (int k = 0; k < KK; ++k) s[k] = 0.f;
        for (int ch = 0; ch < NCH; ++ch) {
            size_t base = ((size_t)(ch * BN + b) * KK) * HW + p;
#pragma unroll
            for (int k = 0; k < KK; ++k)
                s[k] += g_ab_part[base + (size_t)k * HW];
        }
        float mx = -1e30f;
#pragma unroll
        for (int k = 0; k < KK; ++k) {
            s[k] = 2.f * s[k] - asq[k];
            mx = fmaxf(mx, s[k]);
        }
        float sum = 0.f;
#pragma unroll
        for (int k = 0; k < KK; ++k) {
            s[k] = expf(s[k] - mx);
            sum += s[k];
        }
        float inv = 1.f / sum;
#pragma unroll
        for (int k = 0; k < KK; ++k) {
            float m = s[k] * inv;
            maps[((size_t)(b * KK + k)) * HW + p] = m;
            att[k] += m;
        }
    }

    __shared__ float red[256];
#pragma unroll
    for (int k = 0; k < KK; ++k) {
        red[tid] = att[k];
        __syncthreads();
        for (int o = 128; o; o >>= 1) {
            if (tid < o) red[tid] += red[tid + o];
            __syncthreads();
        }
        if (tid == 0) attn[b * KK + k] = red[0];
        __syncthreads();
    }
}

// ---------------------------------------------------------------------------
// Kernel 3: feat[b,c,k] = (1/784) * sum_p maps[b,k,p] * x[b,c,p],
// then * modulation, write feat_mod; also g[b,c] = sum_k feat_mod.
// grid (96 cblk, 32 b), block 256 (8 warps). Warp handles 4 channels;
// lanes stride pixels (coalesced x loads); shfl reduce.
// ---------------------------------------------------------------------------
__global__ void k_feat(const float* __restrict__ x,
                       const float* __restrict__ maps,
                       const float* __restrict__ mod,
                       float* __restrict__ feat) {
    __shared__ float maps_s[KK * HW];
    const int cblk = blockIdx.x;
    const int b    = blockIdx.y;
    const int tid  = threadIdx.x;
    const int warp = tid >> 5;
    const int lane = tid & 31;
    const int cbase = cblk * 32 + warp * 4;

    for (int i = tid; i < KK * HW; i += 256)
        maps_s[i] = maps[(size_t)b * KK * HW + i];
    __syncthreads();

    float acc[4][KK];
#pragma unroll
    for (int j = 0; j < 4; ++j)
#pragma unroll
        for (int k = 0; k < KK; ++k) acc[j][k] = 0.f;

    const float* xb = x + (size_t)b * CC * HW;

    for (int p = lane; p < HW; p += 32) {
        float m[KK];
#pragma unroll
        for (int k = 0; k < KK; ++k) m[k] = maps_s[k * HW + p];
#pragma unroll
        for (int j = 0; j < 4; ++j) {
            float xv = xb[(size_t)(cbase + j) * HW + p];
#pragma unroll
            for (int k = 0; k < KK; ++k)
                acc[j][k] = fmaf(xv, m[k], acc[j][k]);
        }
    }

    // warp reduce all 44 accumulators
#pragma unroll
    for (int j = 0; j < 4; ++j)
#pragma unroll
        for (int k = 0; k < KK; ++k) {
#pragma unroll
            for (int o = 16; o; o >>= 1)
                acc[j][k] += __shfl_down_sync(0xffffffffu, acc[j][k], o);
        }

    if (lane == 0) {
        const float inv_hw = 1.f / (float)HW;
#pragma unroll
        for (int j = 0; j < 4; ++j) {
            int c = cbase + j;
            float gs = 0.f;
#pragma unroll
            for (int k = 0; k < KK; ++k) {
                float v = acc[j][k] * inv_hw * mod[c * KK + k];
                feat[((size_t)b * CC + c) * KK + k] = v;
                gs += v;
            }
            g_g[b * CC + c] = gs;
        }
    }
}

// ---------------------------------------------------------------------------
// Kernel 4: scores[b,n] = sum_c g[b,c] * w_cls[n,c]
// grid (200, 32), block 128
// ---------------------------------------------------------------------------
__global__ void k_scores(const float* __restrict__ wcls,
                         float* __restrict__ scores) {
    const int n = blockIdx.x;
    const int b = blockIdx.y;
    const int tid = threadIdx.x;
    float s = 0.f;
    const float* gb = g_g + b * CC;
    const float* wn = wcls + (size_t)n * CC;
    for (int c = tid; c < CC; c += 128)
        s = fmaf(gb[c], wn[c], s);
    __shared__ float red[128];
    red[tid] = s;
    __syncthreads();
    for (int o = 64; o; o >>= 1) {
        if (tid < o) red[tid] += red[tid + o];
        __syncthreads();
    }
    if (tid == 0) scores[b * NCLS + n] = red[0];
}

// ---------------------------------------------------------------------------
extern "C" void kernel_launch(void* const* d_in, const int* in_sizes, int n_in,
                              void* d_out, int out_size) {
    const float* x    = (const float*)d_in[0];
    const float* wl   = (const float*)d_in[1];
    const float* mod  = (const float*)d_in[2];
    const float* wcls = (const float*)d_in[3];

    float* out    = (float*)d_out;
    float* feat   = out;                                   // (B,C,K)  1,081,344
    float* scores = out + (size_t)BN * CC * KK;            // (B,NC)   6,400
    float* maps   = scores + (size_t)BN * NCLS;            // (B,K,HW) 275,968
    float* attn   = maps + (size_t)BN * KK * HW;           // (B,K)    352

    k_asq<<<KK, 128>>>(wl);
    k_ab<<<dim3(NCH, BN), 196>>>(x, wl);
    k_softmax<<<BN, 256>>>(maps, attn);
    k_feat<<<dim3(CC / 32, BN), 256>>>(x, maps, mod, feat);
    k_scores<<<dim3(NCLS, BN), 128>>>(wcls, scores);
}